// round 17
// baseline (speedup 1.0000x reference)
#include <cuda_runtime.h>
#include <cuda_fp16.h>
#include <math.h>
#include <stdint.h>
#include <cstdint>
#include <cstddef>

// Problem dims
#define E_ 8
#define S_ 64
#define H_ 2048
#define D_ 1024
#define B_ 8192
#define LN_EPS 1e-5f

// GEMM tiling
#define TM 128
#define TN 128
#define TKK 64                          // K per mainloop iteration
#define NGROUPS 16
#define P_MAX (B_ + NGROUPS * TM)       // 10240
#define MTILES (P_MAX / TM)             // 80

#define LDA_S 72                        // As row stride in fp16 (64 + 8 pad)
#define LDB_S 136                       // Bs row stride in fp16 (128 + 8 pad)

#define A_PL (TM * LDA_S)               // 9216 halfs
#define B_PL (TKK * LDB_S)              // 8704 halfs
#define NSTAGE 3                        // cp.async pipeline depth (A16 path)
#define STG_PL (A_PL + B_PL)            // 17920 halfs per stage
#define SMEM_H_TOT (NSTAGE * STG_PL)    // 53760 halfs (covers !A16 layout too)
#define SMEM_BYTES (SMEM_H_TOT * 2 + TM * 4)   // 108032 B; occ 2 = 216 KB

// fp16 weight buffer offsets (in halfs)
#define WH_PW1 0
#define WH_QW1 (WH_PW1 + E_ * S_ * H_)
#define WH_PW2 (WH_QW1 + E_ * S_ * H_)
#define WH_QW2 (WH_PW2 + E_ * H_ * D_)
#define WH_TW1 (WH_QW2 + E_ * H_ * D_)
#define WH_TW2 (WH_TW1 + E_ * D_ * H_)
#define WH_TOT (WH_TW2 + E_ * H_ * D_)

#define N4_SMALL (E_ * S_ * H_ / 4)
#define N4_BIG   (E_ * H_ * D_ / 4)

// Scratch (device globals — no allocation allowed)
__device__ int    g_perm[P_MAX];
__device__ int    g_tile_group[MTILES];
__device__ __half g_wh[WH_TOT];
__device__ __half g_h1h[(size_t)B_ * H_];
__device__ __half g_h2h[(size_t)B_ * H_];
__device__ __half g_midh[(size_t)B_ * D_];
__device__ float  g_mid[(size_t)B_ * D_];

// ---------------------------------------------------------------------------
// Shared converter body
// ---------------------------------------------------------------------------
__device__ __forceinline__ void cvt_pair(int cb, int nblk, int tid,
                                         const float* srcA, __half* dstA,
                                         const float* srcB, __half* dstB, int n4)
{
    int half_blk = nblk >> 1;
    const float4* s;
    __half* d;
    int id;
    if (cb < half_blk) { s = (const float4*)srcA; d = dstA; id = cb; }
    else               { s = (const float4*)srcB; d = dstB; id = cb - half_blk; }
    int stride = half_blk * 256;
    for (int i = id * 256 + tid; i < n4; i += stride) {
        float4 v = s[i];
        __half h[4];
        h[0] = __float2half_rn(v.x); h[1] = __float2half_rn(v.y);
        h[2] = __float2half_rn(v.z); h[3] = __float2half_rn(v.w);
        *(uint2*)(d + (size_t)4 * i) = *(uint2*)h;
    }
}

// ---------------------------------------------------------------------------
// Group builder (block 0) + small-weight conversion (blocks 1..N).
// ---------------------------------------------------------------------------
__global__ void build_groups_cvt(const int* __restrict__ hp, const int* __restrict__ ei,
                                 const float* __restrict__ pw1, __half* __restrict__ pw1h,
                                 const float* __restrict__ qw1, __half* __restrict__ qw1h)
{
    int t = threadIdx.x;
    if (blockIdx.x > 0) {
        cvt_pair(blockIdx.x - 1, gridDim.x - 1, t, pw1, pw1h, qw1, qw1h, N4_SMALL);
        return;
    }

    __shared__ int cnt[NGROUPS];
    __shared__ int cur[NGROUPS];
    if (t < NGROUPS) cnt[t] = 0;
    __syncthreads();

    for (int r = t; r < B_; r += blockDim.x) {
        int g = ei[r] * 2 + (hp[r] != 0);
        atomicAdd(&cnt[g], 1);
    }
    for (int i = t; i < P_MAX; i += blockDim.x) g_perm[i] = -1;
    __syncthreads();

    if (t == 0) {
        int off = 0;
        for (int g = 0; g < NGROUPS; g++) {
            cur[g] = off;
            int ntile = (cnt[g] + TM - 1) / TM;
            int t0 = off / TM;
            for (int k = 0; k < ntile; k++) g_tile_group[t0 + k] = g;
            off += ntile * TM;
        }
        for (int k = off / TM; k < MTILES; k++) g_tile_group[k] = -1;
    }
    __syncthreads();

    for (int r = t; r < B_; r += blockDim.x) {
        int g = ei[r] * 2 + (hp[r] != 0);
        int pos = atomicAdd(&cur[g], 1);
        g_perm[pos] = r;
    }
}

// ---------------------------------------------------------------------------
// PTX helpers
// ---------------------------------------------------------------------------
__device__ __forceinline__ void ldsm_x4(uint32_t* r, uint32_t addr) {
    asm volatile("ldmatrix.sync.aligned.m8n8.x4.shared.b16 {%0,%1,%2,%3}, [%4];\n"
                 : "=r"(r[0]), "=r"(r[1]), "=r"(r[2]), "=r"(r[3]) : "r"(addr));
}
__device__ __forceinline__ void ldsm_x4_t(uint32_t* r, uint32_t addr) {
    asm volatile("ldmatrix.sync.aligned.m8n8.x4.trans.shared.b16 {%0,%1,%2,%3}, [%4];\n"
                 : "=r"(r[0]), "=r"(r[1]), "=r"(r[2]), "=r"(r[3]) : "r"(addr));
}
__device__ __forceinline__ void mma_fp16(float* c, const uint32_t* a,
                                         uint32_t b0, uint32_t b1) {
    asm volatile("mma.sync.aligned.m16n8k16.row.col.f32.f16.f16.f32 "
                 "{%0,%1,%2,%3}, {%4,%5,%6,%7}, {%8,%9}, {%0,%1,%2,%3};\n"
                 : "+f"(c[0]), "+f"(c[1]), "+f"(c[2]), "+f"(c[3])
                 : "r"(a[0]), "r"(a[1]), "r"(a[2]), "r"(a[3]), "r"(b0), "r"(b1));
}
__device__ __forceinline__ void split_fp16(float a, __half& hi, __half& lo) {
    hi = __float2half_rn(a);
    lo = __float2half_rn(a - __half2float(hi));
}
__device__ __forceinline__ void cp16(uint32_t d, const void* s) {
    asm volatile("cp.async.cg.shared.global [%0], [%1], 16;" :: "r"(d), "l"(s));
}
__device__ __forceinline__ void cp16z(uint32_t d, const void* s, uint32_t sz) {
    asm volatile("cp.async.cg.shared.global [%0], [%1], 16, %2;" :: "r"(d), "l"(s), "r"(sz));
}
#define CP_COMMIT() asm volatile("cp.async.commit_group;" ::: "memory")
#define CP_WAIT0()  asm volatile("cp.async.wait_group 0;" ::: "memory")
#define CP_WAIT1()  asm volatile("cp.async.wait_group 1;" ::: "memory")

// ---------------------------------------------------------------------------
// Grouped GEMM, fp16 tensor cores.
// A16: single-fp16 A, 3-stage cp.async pipeline, TKK=64 (nk >= 16 always).
// !A16 (stage 1 only, nk=1): fp32 A, exact 2-term split, single buffer.
// Extra blockIdx.y rows (>= MTILES) convert next-stage weights concurrently.
// ---------------------------------------------------------------------------
template<bool GELU, bool A16, bool OUT16>
__global__ __launch_bounds__(256, 2)
void gemm_tc(const float* __restrict__ Af,
             const __half* __restrict__ Ah,
             int K, int N,
             const __half* __restrict__ Wp, const __half* __restrict__ Wq,
             const float* __restrict__ bp, const float* __restrict__ bq,
             float* __restrict__ OutF, __half* __restrict__ OutH,
             const float* __restrict__ cvA, __half* __restrict__ cvAd,
             const float* __restrict__ cvB, __half* __restrict__ cvBd)
{
    int mt = blockIdx.y;
    int t = threadIdx.x;

    if (mt >= MTILES) {
        int nblk = (gridDim.y - MTILES) * gridDim.x;
        int cb   = (mt - MTILES) * gridDim.x + blockIdx.x;
        cvt_pair(cb, nblk, t, cvA, cvAd, cvB, cvBd, N4_BIG);
        return;
    }

    int g = g_tile_group[mt];
    if (g < 0) return;
    int e = g >> 1, sel = g & 1;
    const __half* W   = (sel ? Wq : Wp) + (size_t)e * K * N;
    const float* bias = (sel ? bq : bp) + (size_t)e * N;
    int n0 = blockIdx.x * TN;

    extern __shared__ __align__(16) __half dsm[];
    int* rows_s = (int*)(dsm + SMEM_H_TOT);

    if (t < TM) rows_s[t] = g_perm[mt * TM + t];
    __syncthreads();

    int lane = t & 31;
    int wid  = t >> 5;
    int wr = wid & 3;
    int wc = wid >> 2;

    uint32_t smem_u = (uint32_t)__cvta_generic_to_shared(dsm);

    // Loader mappings (TKK = 64)
    // A: thread -> (row = t>>1, 32 consecutive halfs at (t&1)*32)
    int ia_row = t >> 1;
    int ia_col = (t & 1) << 5;              // 0 or 32 halfs
    int rowA = rows_s[ia_row];
    uint32_t szA = (rowA >= 0) ? 16u : 0u;
    const __half* Ah_p = (rowA >= 0) ? Ah + (size_t)rowA * K + ia_col : Ah;
    const float*  Af_p = (rowA >= 0 && !A16) ? Af + (size_t)rowA * K + ia_col : (const float*)0;

    // B: thread -> (k row = t>>2, 32 consecutive halfs at (t&3)*32)
    int ib_k = t >> 2;                      // 0..63
    int ib_n = (t & 3) << 5;                // 0,32,64,96
    const __half* Bp = W + (size_t)ib_k * N + n0 + ib_n;

    uint32_t dA_off = (uint32_t)(ia_row * LDA_S + ia_col) * 2u;
    uint32_t dB_off = (uint32_t)(ib_k * LDB_S + ib_n) * 2u;

    // ldmatrix address components
    int a_row_off = lane & 15;
    int a_col_off = (lane >> 4) << 3;
    int bm = lane >> 3;
    int b_krow_off = ((bm & 1) << 3) + (lane & 7);
    int b_ncol_off = (bm >> 1) << 3;

    float acc[2][8][4];
    #pragma unroll
    for (int mi = 0; mi < 2; mi++)
        #pragma unroll
        for (int ni = 0; ni < 8; ni++)
            #pragma unroll
            for (int q = 0; q < 4; q++) acc[mi][ni][q] = 0.0f;

    // A16 stage layout: stage s -> A at s*STG_PL, B at s*STG_PL + A_PL
    auto issue_tile = [&](int stg, int k0) {
        uint32_t base = smem_u + (uint32_t)(stg * STG_PL) * 2u;
        uint32_t dh = base + dA_off;
        const __half* sA = Ah_p + k0;
        cp16z(dh,      sA,      szA);
        cp16z(dh + 16, sA + 8,  szA);
        cp16z(dh + 32, sA + 16, szA);
        cp16z(dh + 48, sA + 24, szA);
        uint32_t db = base + (uint32_t)A_PL * 2u + dB_off;
        const __half* sB = Bp + (size_t)k0 * N;
        cp16(db,      sB);
        cp16(db + 16, sB + 8);
        cp16(db + 32, sB + 16);
        cp16(db + 48, sB + 24);
    };

    // compute one TKK=64 tile; aLo only used when !A16
    auto compute = [&](uint32_t aBaseHi, uint32_t aBaseLo, uint32_t bBase) {
        #pragma unroll
        for (int ks = 0; ks < 4; ks++) {
            uint32_t a_hi[2][4], a_lo[2][4], bfr[4];
            #pragma unroll
            for (int mi = 0; mi < 2; mi++) {
                int row = wr * 32 + mi * 16 + a_row_off;
                int cb  = ks * 16 + a_col_off;
                uint32_t off = (uint32_t)(row * LDA_S + cb) * 2u;
                ldsm_x4(a_hi[mi], aBaseHi + off);
                if (!A16) ldsm_x4(a_lo[mi], aBaseLo + off);
            }
            int krow = ks * 16 + b_krow_off;
            #pragma unroll
            for (int j = 0; j < 4; j++) {
                int ncol = wc * 64 + j * 16 + b_ncol_off;
                uint32_t off = (uint32_t)(krow * LDB_S + ncol) * 2u;
                ldsm_x4_t(bfr, bBase + off);
                #pragma unroll
                for (int mi = 0; mi < 2; mi++) {
                    mma_fp16(acc[mi][2*j+0], a_hi[mi], bfr[0], bfr[1]);
                    mma_fp16(acc[mi][2*j+1], a_hi[mi], bfr[2], bfr[3]);
                    if (!A16) {
                        mma_fp16(acc[mi][2*j+0], a_lo[mi], bfr[0], bfr[1]);
                        mma_fp16(acc[mi][2*j+1], a_lo[mi], bfr[2], bfr[3]);
                    }
                }
            }
        }
    };

    int nk = K / TKK;

    if (A16) {
        // 3-stage pipeline (nk >= 16 for all A16 stages).
        issue_tile(0, 0);        CP_COMMIT();
        issue_tile(1, TKK);      CP_COMMIT();
        int stg = 0;
        for (int it = 0; it < nk; it++) {
            CP_WAIT1();            // tile it's group arrived (<=1 pending)
            __syncthreads();       // visible to all; buf (it-1)%3 free
            int nx = it + NSTAGE - 1;
            int nstg = stg + NSTAGE - 1; if (nstg >= NSTAGE) nstg -= NSTAGE;
            if (nx < nk) issue_tile(nstg, nx * TKK);
            CP_COMMIT();           // commit every iter to keep counts aligned
            uint32_t base = smem_u + (uint32_t)(stg * STG_PL) * 2u;
            compute(base, 0u, base + (uint32_t)A_PL * 2u);
            if (++stg == NSTAGE) stg = 0;
        }
    } else {
        // stage 1 (K=64, nk=1): single buffer, fp32 A with exact 2-term split.
        uint32_t aHi = smem_u;
        uint32_t aLo = smem_u + (uint32_t)A_PL * 2u;
        uint32_t bB  = smem_u + (uint32_t)(2 * A_PL) * 2u;
        for (int it = 0; it < nk; it++) {
            int k0 = it * TKK;
            float va[32];
            #pragma unroll
            for (int i = 0; i < 8; i++) {
                float4 v = Af_p ? *(const float4*)(Af_p + k0 + i * 4)
                                : make_float4(0.f, 0.f, 0.f, 0.f);
                va[i*4+0] = v.x; va[i*4+1] = v.y; va[i*4+2] = v.z; va[i*4+3] = v.w;
            }
            uint32_t db = bB + dB_off;
            const __half* sB = Bp + (size_t)k0 * N;
            cp16(db, sB); cp16(db + 16, sB + 8);
            cp16(db + 32, sB + 16); cp16(db + 48, sB + 24);
            CP_COMMIT();

            __half h[32], l[32];
            #pragma unroll
            for (int i = 0; i < 32; i++) split_fp16(va[i], h[i], l[i]);
            uint4* dh = (uint4*)((char*)dsm + (aHi - smem_u) + dA_off);
            uint4* dl = (uint4*)((char*)dsm + (aLo - smem_u) + dA_off);
            dh[0] = *(uint4*)&h[0];  dh[1] = *(uint4*)&h[8];
            dh[2] = *(uint4*)&h[16]; dh[3] = *(uint4*)&h[24];
            dl[0] = *(uint4*)&l[0];  dl[1] = *(uint4*)&l[8];
            dl[2] = *(uint4*)&l[16]; dl[3] = *(uint4*)&l[24];

            CP_WAIT0();
            __syncthreads();
            compute(aHi, aLo, bB);
            __syncthreads();
        }
    }

    // ---- epilogue ----
    #pragma unroll
    for (int mi = 0; mi < 2; mi++) {
        #pragma unroll
        for (int half = 0; half < 2; half++) {
            int mrow = wr * 32 + mi * 16 + half * 8 + (lane >> 2);
            int r = rows_s[mrow];
            if (r < 0) continue;
            #pragma unroll
            for (int ni = 0; ni < 8; ni++) {
                int col = n0 + wc * 64 + ni * 8 + ((lane & 3) << 1);
                float v0 = acc[mi][ni][half * 2 + 0] + bias[col];
                float v1 = acc[mi][ni][half * 2 + 1] + bias[col + 1];
                if (GELU) {
                    v0 = 0.5f * v0 * (1.0f + erff(v0 * 0.7071067811865475f));
                    v1 = 0.5f * v1 * (1.0f + erff(v1 * 0.7071067811865475f));
                }
                if (OUT16) {
                    __half hh[2] = {__float2half_rn(v0), __float2half_rn(v1)};
                    *(uint32_t*)(OutH + (size_t)r * N + col) = *(uint32_t*)hh;
                } else {
                    *(float2*)(OutF + (size_t)r * N + col) = make_float2(v0, v1);
                }
            }
        }
    }
}

// ---------------------------------------------------------------------------
// LayerNorm over D=1024; reads fp32 mid, writes fp16 plane.
// ---------------------------------------------------------------------------
__global__ __launch_bounds__(256)
void layernorm_k(const int* __restrict__ ei,
                 const float* __restrict__ ln_g, const float* __restrict__ ln_b,
                 const float* __restrict__ mid,
                 __half* __restrict__ outh)
{
    int r = blockIdx.x;
    int e = ei[r];
    const float* x = mid + (size_t)r * D_;
    int t = threadIdx.x;

    float v[4];
    float s = 0.f, ss = 0.f;
    #pragma unroll
    for (int i = 0; i < 4; i++) {
        v[i] = x[t + i * 256];
        s += v[i];
        ss += v[i] * v[i];
    }
    #pragma unroll
    for (int o = 16; o; o >>= 1) {
        s  += __shfl_xor_sync(0xffffffffu, s,  o);
        ss += __shfl_xor_sync(0xffffffffu, ss, o);
    }
    __shared__ float red[2][8];
    int w = t >> 5, l = t & 31;
    if (l == 0) { red[0][w] = s; red[1][w] = ss; }
    __syncthreads();
    float S = 0.f, SS = 0.f;
    #pragma unroll
    for (int i = 0; i < 8; i++) { S += red[0][i]; SS += red[1][i]; }

    float mu  = S * (1.0f / D_);
    float var = SS * (1.0f / D_) - mu * mu;
    float rstd = rsqrtf(var + LN_EPS);

    const float* gg = ln_g + (size_t)e * D_;
    const float* bb = ln_b + (size_t)e * D_;
    #pragma unroll
    for (int i = 0; i < 4; i++) {
        int c = t + i * 256;
        float y = (v[i] - mu) * rstd * gg[c] + bb[c];
        outh[(size_t)r * D_ + c] = __float2half_rn(y);
    }
}

// ---------------------------------------------------------------------------
extern "C" void kernel_launch(void* const* d_in, const int* in_sizes, int n_in,
                              void* d_out, int out_size)
{
    const float* x   = (const float*)d_in[0];
    const int*   hp  = (const int*)d_in[1];
    const int*   ei  = (const int*)d_in[2];
    const float* pw1 = (const float*)d_in[3];
    const float* pb1 = (const float*)d_in[4];
    const float* pw2 = (const float*)d_in[5];
    const float* pb2 = (const float*)d_in[6];
    const float* qw1 = (const float*)d_in[7];
    const float* qb1 = (const float*)d_in[8];
    const float* qw2 = (const float*)d_in[9];
    const float* qb2 = (const float*)d_in[10];
    const float* lng = (const float*)d_in[11];
    const float* lnb = (const float*)d_in[12];
    const float* tw1 = (const float*)d_in[13];
    const float* tb1 = (const float*)d_in[14];
    const float* tw2 = (const float*)d_in[15];
    const float* tb2 = (const float*)d_in[16];
    float* out = (float*)d_out;

    __half *wh, *h1h, *h2h, *midh;
    float *mid;
    cudaGetSymbolAddress((void**)&wh,   g_wh);
    cudaGetSymbolAddress((void**)&h1h,  g_h1h);
    cudaGetSymbolAddress((void**)&h2h,  g_h2h);
    cudaGetSymbolAddress((void**)&midh, g_midh);
    cudaGetSymbolAddress((void**)&mid,  g_mid);

    static bool attr_done = false;
    if (!attr_done) {
        cudaFuncSetAttribute(gemm_tc<true , false, true >, cudaFuncAttributeMaxDynamicSharedMemorySize, SMEM_BYTES);
        cudaFuncSetAttribute(gemm_tc<false, true , false>, cudaFuncAttributeMaxDynamicSharedMemorySize, SMEM_BYTES);
        cudaFuncSetAttribute(gemm_tc<true , true , true >, cudaFuncAttributeMaxDynamicSharedMemorySize, SMEM_BYTES);
        attr_done = true;
    }

    // Group build (block 0) + pw1/qw1 fp16 conversion (512 extra blocks)
    build_groups_cvt<<<1 + 512, 256>>>(hp, ei, pw1, wh + WH_PW1, qw1, wh + WH_QW1);

    // Stage 1: h1(fp16) = gelu(x @ {p,q}w1 + b1)   K=64, fp32 A, 2-term exact.
    // Extra 64 grid rows convert pw2/qw2 for stage 2.
    gemm_tc<true , false, true ><<<dim3(H_ / TN, MTILES + 64), 256, SMEM_BYTES>>>(
        x, (const __half*)0, S_, H_,
        wh + WH_PW1, wh + WH_QW1, pb1, qb1,
        (float*)0, h1h,
        pw2, wh + WH_PW2, qw2, wh + WH_QW2);
    // Stage 2: mid = h1 @ {p,q}w2 + b2             K=2048, 3-stage pipeline.
    // Extra 128 grid rows convert tw1/tw2 for stages 4/5.
    gemm_tc<false, true , false><<<dim3(D_ / TN, MTILES + 128), 256, SMEM_BYTES>>>(
        (const float*)0, h1h, H_, D_,
        wh + WH_PW2, wh + WH_QW2, pb2, qb2,
        mid, (__half*)0,
        tw1, wh + WH_TW1, tw2, wh + WH_TW2);
    // Stage 3: layernorm -> fp16 plane
    layernorm_k<<<B_, 256>>>(ei, lng, lnb, mid, midh);
    // Stage 4: h2(fp16) = gelu(mid @ tw1 + tb1)    K=1024
    gemm_tc<true , true , true ><<<dim3(H_ / TN, MTILES), 256, SMEM_BYTES>>>(
        (const float*)0, midh, D_, H_,
        wh + WH_TW1, wh + WH_TW1, tb1, tb1,
        (float*)0, h2h,
        (const float*)0, (__half*)0, (const float*)0, (__half*)0);
    // Stage 5: out = h2 @ tw2 + tb2                K=2048
    gemm_tc<false, true , false><<<dim3(D_ / TN, MTILES), 256, SMEM_BYTES>>>(
        (const float*)0, h2h, H_, D_,
        wh + WH_TW2, wh + WH_TW2, tb2, tb2,
        out, (__half*)0,
        (const float*)0, (__half*)0, (const float*)0, (__half*)0);
}